// round 7
// baseline (speedup 1.0000x reference)
#include <cuda_runtime.h>
#include <cstdint>

// x (8,3,1024,1024) f32 -> out (8,3,512,512) f32
// d_in: [0]=x, [1]=w0 (K0*512), [2]=fov0 (K0*512 i32)  -> dim2 (H, vertical)
//       [3]=w1 (K1*512), [4]=fov1 (K1*512 i32)         -> dim3 (W, horizontal)
//
// R7: same streaming-accumulator structure as R6, but tuned for 6 blocks/SM
// (was 5): __launch_bounds__(256,6) + vertical weights moved to smem to get
// regs <= 42. Grid 1536 then runs in 2 waves (was 3, with a 7.5%-full tail),
// and one extra resident block per SM overlaps phase-1 DRAM with phase-2 LDS.

#define BC     24
#define IN_H   1024
#define IN_W   1024
#define OUT_H  512
#define OUT_W  512
#define G      8           // output rows per block

// ---------------------------------------------------------------------------
template<int K>
__global__ __launch_bounds__(256, 6)
void fused_stream_kernel(const float* __restrict__ x,
                         const float* __restrict__ w0,
                         const int*   __restrict__ fov0,
                         const float* __restrict__ w1,
                         const int*   __restrict__ fov1,
                         float*       __restrict__ out,
                         int K1)
{
    __shared__ float tile[G][IN_W];              // 32 KB, parity-permuted
    __shared__ float swv[K];                     // vertical weights (broadcast)

    const int t   = threadIdx.x;                 // 0..255
    const int bc  = blockIdx.y;
    const int oh0 = blockIdx.x * G;

    const float4* xb = reinterpret_cast<const float4*>(x + (size_t)bc * IN_H * IN_W);

    // ---- regularity check: fov0[j][oh0+i] == start + 2i + j, w0 oh-invariant
    const int start = fov0[oh0];
    int flag = 1;
    if (t < K * G) {
        const int j  = t / G;
        const int i  = t % G;
        const int oh = oh0 + i;
        flag  = (fov0[j * OUT_H + oh] == start + 2 * i + j);
        flag &= (w0  [j * OUT_H + oh] == w0[j * OUT_H + oh0]);
    }
    if (t < K) swv[t] = w0[t * OUT_H + oh0];     // before the barrier below
    const int regular = __syncthreads_and(flag);

    if (regular) {
        // ---------- Phase 1a: stream K+2(G-1) rows into G accumulators ------
        constexpr int NROWS = K + 2 * (G - 1);   // 22 for K=8

        float4 acc[G];
#pragma unroll
        for (int i = 0; i < G; ++i) { acc[i].x = acc[i].y = acc[i].z = acc[i].w = 0.f; }

#pragma unroll
        for (int m = 0; m < NROWS; ++m) {
            const float4 v = xb[(size_t)(start + m) * (IN_W / 4) + t];
#pragma unroll
            for (int i = 0; i < G; ++i) {
                const int j = m - 2 * i;          // tap index for output i
                if (j >= 0 && j < K) {            // compile-time pruned
                    const float w = swv[j];       // smem broadcast (saves regs)
                    acc[i].x += w * v.x;
                    acc[i].y += w * v.y;
                    acc[i].z += w * v.z;
                    acc[i].w += w * v.w;
                }
            }
            // retire accumulator i when its window closes (m == 2i+K-1)
            if (m >= K - 1 && ((m - (K - 1)) & 1) == 0) {
                const int i = (m - (K - 1)) / 2;
                float2 e; e.x = acc[i].x; e.y = acc[i].z;
                float2 o; o.x = acc[i].y; o.y = acc[i].w;
                reinterpret_cast<float2*>(tile[i])[t]       = e;
                reinterpret_cast<float2*>(tile[i] + 512)[t] = o;
            }
        }
    } else {
        // ---------- Phase 1b: generic gather (boundary blocks) ----------
        for (int i = 0; i < G; ++i) {
            const int oh = oh0 + i;
            float ax = 0.f, ay = 0.f, az = 0.f, aw = 0.f;
            for (int j = 0; j < K; ++j) {
                const int   r = fov0[j * OUT_H + oh];
                const float w = w0  [j * OUT_H + oh];
                const float4 v = xb[(size_t)r * (IN_W / 4) + t];
                ax += w * v.x;
                ay += w * v.y;
                az += w * v.z;
                aw += w * v.w;
            }
            float2 e; e.x = ax; e.y = az;
            float2 o; o.x = ay; o.y = aw;
            reinterpret_cast<float2*>(tile[i])[t]       = e;
            reinterpret_cast<float2*>(tile[i] + 512)[t] = o;
        }
    }
    __syncthreads();

    // ---------------- Phase 2: horizontal resample from permuted smem -------
    float a0[G], a1[G];
#pragma unroll
    for (int i = 0; i < G; ++i) { a0[i] = 0.f; a1[i] = 0.f; }

    for (int j = 0; j < K1; ++j) {
        const float w_a = w1  [j * OUT_W + t];
        const float w_b = w1  [j * OUT_W + t + 256];
        const int   f_a = fov1[j * OUT_W + t];
        const int   f_b = fov1[j * OUT_W + t + 256];
        const int p_a = (f_a >> 1) + ((f_a & 1) << 9);
        const int p_b = (f_b >> 1) + ((f_b & 1) << 9);
#pragma unroll
        for (int i = 0; i < G; ++i) {
            a0[i] += w_a * tile[i][p_a];
            a1[i] += w_b * tile[i][p_b];
        }
    }

#pragma unroll
    for (int i = 0; i < G; ++i) {
        float* orow = out + ((size_t)bc * OUT_H + oh0 + i) * OUT_W;
        orow[t]       = a0[i];
        orow[t + 256] = a1[i];
    }
}

// ---------------------------------------------------------------------------
// Generic fallback kernel for K0 outside the template set.
__global__ __launch_bounds__(256)
void fused_generic_kernel(const float* __restrict__ x,
                          const float* __restrict__ w0,
                          const int*   __restrict__ fov0,
                          const float* __restrict__ w1,
                          const int*   __restrict__ fov1,
                          float*       __restrict__ out,
                          int K0, int K1)
{
    __shared__ float tile[G][IN_W];
    const int t   = threadIdx.x;
    const int bc  = blockIdx.y;
    const int oh0 = blockIdx.x * G;
    const float4* xb = reinterpret_cast<const float4*>(x + (size_t)bc * IN_H * IN_W);

    for (int i = 0; i < G; ++i) {
        const int oh = oh0 + i;
        float ax = 0.f, ay = 0.f, az = 0.f, aw = 0.f;
        for (int j = 0; j < K0; ++j) {
            const int   r = fov0[j * OUT_H + oh];
            const float w = w0  [j * OUT_H + oh];
            const float4 v = xb[(size_t)r * (IN_W / 4) + t];
            ax += w * v.x; ay += w * v.y; az += w * v.z; aw += w * v.w;
        }
        float2 e; e.x = ax; e.y = az;
        float2 o; o.x = ay; o.y = aw;
        reinterpret_cast<float2*>(tile[i])[t]       = e;
        reinterpret_cast<float2*>(tile[i] + 512)[t] = o;
    }
    __syncthreads();

    float a0[G], a1[G];
#pragma unroll
    for (int i = 0; i < G; ++i) { a0[i] = 0.f; a1[i] = 0.f; }
    for (int j = 0; j < K1; ++j) {
        const float w_a = w1  [j * OUT_W + t];
        const float w_b = w1  [j * OUT_W + t + 256];
        const int   f_a = fov1[j * OUT_W + t];
        const int   f_b = fov1[j * OUT_W + t + 256];
        const int p_a = (f_a >> 1) + ((f_a & 1) << 9);
        const int p_b = (f_b >> 1) + ((f_b & 1) << 9);
#pragma unroll
        for (int i = 0; i < G; ++i) {
            a0[i] += w_a * tile[i][p_a];
            a1[i] += w_b * tile[i][p_b];
        }
    }
#pragma unroll
    for (int i = 0; i < G; ++i) {
        float* orow = out + ((size_t)bc * OUT_H + oh0 + i) * OUT_W;
        orow[t]       = a0[i];
        orow[t + 256] = a1[i];
    }
}

// ---------------------------------------------------------------------------

extern "C" void kernel_launch(void* const* d_in, const int* in_sizes, int n_in,
                              void* d_out, int out_size)
{
    const float* x    = (const float*)d_in[0];
    const float* w0   = (const float*)d_in[1];
    const int*   fov0 = (const int*)  d_in[2];
    const float* w1   = (const float*)d_in[3];
    const int*   fov1 = (const int*)  d_in[4];
    float*       out  = (float*)d_out;

    const int K0 = in_sizes[1] / OUT_H;   // vertical taps
    const int K1 = in_sizes[3] / OUT_W;   // horizontal taps

    dim3 grid(OUT_H / G, BC);

    switch (K0) {
    case 6:  fused_stream_kernel< 6><<<grid, 256>>>(x, w0, fov0, w1, fov1, out, K1); break;
    case 7:  fused_stream_kernel< 7><<<grid, 256>>>(x, w0, fov0, w1, fov1, out, K1); break;
    case 8:  fused_stream_kernel< 8><<<grid, 256>>>(x, w0, fov0, w1, fov1, out, K1); break;
    case 9:  fused_stream_kernel< 9><<<grid, 256>>>(x, w0, fov0, w1, fov1, out, K1); break;
    case 10: fused_stream_kernel<10><<<grid, 256>>>(x, w0, fov0, w1, fov1, out, K1); break;
    case 11: fused_stream_kernel<11><<<grid, 256>>>(x, w0, fov0, w1, fov1, out, K1); break;
    case 12: fused_stream_kernel<12><<<grid, 256>>>(x, w0, fov0, w1, fov1, out, K1); break;
    default: fused_generic_kernel<<<grid, 256>>>(x, w0, fov0, w1, fov1, out, K0, K1); break;
    }
}

// round 8
// speedup vs baseline: 1.0971x; 1.0971x over previous
#include <cuda_runtime.h>
#include <cstdint>

// x (8,3,1024,1024) f32 -> out (8,3,512,512) f32
// d_in: [0]=x, [1]=w0 (K0*512), [2]=fov0 (K0*512 i32)  -> dim2 (H, vertical)
//       [3]=w1 (K1*512), [4]=fov1 (K1*512 i32)         -> dim3 (W, horizontal)
//
// R8: phase 1 = R6 streaming accumulators (register weights, 5 blk/SM).
//     phase 2 = regularity-specialized: interior threads read their tap
//     window via 4 aligned LDS.128 (conflict-free, uniform alignment branch)
//     with K register weights; mirror-boundary threads take a scalar
//     gather fallback. Tile is plain layout with +/-16-float padding.

#define BC     24
#define IN_H   1024
#define IN_W   1024
#define OUT_H  512
#define OUT_W  512
#define G      8            // output rows per block
#define PADW   16           // tile row padding (floats) on each side
#define TROW   (IN_W + 2 * PADW)

// ---------------------------------------------------------------------------
// Fast horizontal rows: O = (s1 & 3), compile-time. Each thread produces
// outputs (ow0, ow0+1) for all G rows from NQ aligned float4 smem loads.
template<int K, int O>
__device__ __forceinline__
void hfast_rows(const float tile[G][TROW], int wstart,
                const float* __restrict__ wh,
                float* __restrict__ outp /* &out[bc][oh0][ow0] */)
{
    constexpr int NQ = (K + 8) / 4;       // float4 loads covering idx O+K+1
#pragma unroll
    for (int i = 0; i < G; ++i) {
        const float4* rp = reinterpret_cast<const float4*>(tile[i] + PADW) + wstart;
        float r[NQ * 4];
#pragma unroll
        for (int q = 0; q < NQ; ++q) {
            const float4 v = rp[q];
            r[4 * q + 0] = v.x; r[4 * q + 1] = v.y;
            r[4 * q + 2] = v.z; r[4 * q + 3] = v.w;
        }
        float a0 = 0.f, a1 = 0.f;
#pragma unroll
        for (int j = 0; j < K; ++j) {
            a0 += wh[j] * r[O + j];
            a1 += wh[j] * r[O + 2 + j];
        }
        float2 res; res.x = a0; res.y = a1;
        *reinterpret_cast<float2*>(outp + (size_t)i * OUT_W) = res;
    }
}

// ---------------------------------------------------------------------------
template<int K>
__global__ __launch_bounds__(256, 5)
void fused_stream_kernel(const float* __restrict__ x,
                         const float* __restrict__ w0,
                         const int*   __restrict__ fov0,
                         const float* __restrict__ w1,
                         const int*   __restrict__ fov1,
                         float*       __restrict__ out)
{
    __shared__ float tile[G][TROW];              // ~33 KB, plain + padded

    const int t   = threadIdx.x;                 // 0..255
    const int bc  = blockIdx.y;
    const int oh0 = blockIdx.x * G;

    const float4* xb = reinterpret_cast<const float4*>(x + (size_t)bc * IN_H * IN_W);

    // ---- vertical regularity: fov0[j][oh0+i] == start + 2i + j, w0 oh-invar.
    const int start = fov0[oh0];
    int flag = 1;
    if (t < K * G) {
        const int j  = t / G;
        const int i  = t % G;
        const int oh = oh0 + i;
        flag  = (fov0[j * OUT_H + oh] == start + 2 * i + j);
        flag &= (w0  [j * OUT_H + oh] == w0[j * OUT_H + oh0]);
    }
    const int regular = __syncthreads_and(flag);

    if (regular) {
        // ---------- Phase 1a: stream K+2(G-1) rows into G accumulators ------
        constexpr int NROWS = K + 2 * (G - 1);

        float wv[K];
#pragma unroll
        for (int j = 0; j < K; ++j) wv[j] = w0[j * OUT_H + oh0];

        float4 acc[G];
#pragma unroll
        for (int i = 0; i < G; ++i) { acc[i].x = acc[i].y = acc[i].z = acc[i].w = 0.f; }

#pragma unroll
        for (int m = 0; m < NROWS; ++m) {
            const float4 v = xb[(size_t)(start + m) * (IN_W / 4) + t];
#pragma unroll
            for (int i = 0; i < G; ++i) {
                const int j = m - 2 * i;
                if (j >= 0 && j < K) {
                    acc[i].x += wv[j] * v.x;
                    acc[i].y += wv[j] * v.y;
                    acc[i].z += wv[j] * v.z;
                    acc[i].w += wv[j] * v.w;
                }
            }
            if (m >= K - 1 && ((m - (K - 1)) & 1) == 0) {
                const int i = (m - (K - 1)) / 2;
                reinterpret_cast<float4*>(tile[i] + PADW)[t] = acc[i];
            }
        }
    } else {
        // ---------- Phase 1b: generic gather (boundary blocks) ----------
        for (int i = 0; i < G; ++i) {
            const int oh = oh0 + i;
            float ax = 0.f, ay = 0.f, az = 0.f, aw = 0.f;
            for (int j = 0; j < K; ++j) {
                const int   r = fov0[j * OUT_H + oh];
                const float w = w0  [j * OUT_H + oh];
                const float4 v = xb[(size_t)r * (IN_W / 4) + t];
                ax += w * v.x; ay += w * v.y; az += w * v.z; aw += w * v.w;
            }
            float4 r4; r4.x = ax; r4.y = ay; r4.z = az; r4.w = aw;
            reinterpret_cast<float4*>(tile[i] + PADW)[t] = r4;
        }
    }
    __syncthreads();

    // ---------------- Phase 2: horizontal resample ---------------------------
    const int ow0 = 2 * t;
    const int s1  = fov1[256] - 512;             // reference interior column

    float wh[K];
#pragma unroll
    for (int j = 0; j < K; ++j) wh[j] = w1[j * OUT_W + 256];

    // per-thread regularity check for its two columns (vectorized)
    int ok = 1;
#pragma unroll
    for (int j = 0; j < K; ++j) {
        const int2   fv = *reinterpret_cast<const int2*>(fov1 + j * OUT_W + ow0);
        const float2 wv = *reinterpret_cast<const float2*>(w1  + j * OUT_W + ow0);
        ok &= (fv.x == s1 + 2 * ow0 + j) & (fv.y == s1 + 2 * ow0 + 2 + j);
        ok &= (wv.x == wh[j]) & (wv.y == wh[j]);
    }

    float* outp = out + ((size_t)bc * OUT_H + oh0) * OUT_W + ow0;

    if (ok) {
        const int o      = s1 & 3;               // uniform across entire grid
        const int wstart = (s1 + 4 * t) >> 2;    // aligned float4 index (floors)
        if      (o == 0) hfast_rows<K, 0>(tile, wstart, wh, outp);
        else if (o == 1) hfast_rows<K, 1>(tile, wstart, wh, outp);
        else if (o == 2) hfast_rows<K, 2>(tile, wstart, wh, outp);
        else             hfast_rows<K, 3>(tile, wstart, wh, outp);
    } else {
        // boundary columns: scalar gather with per-column weights
        for (int i = 0; i < G; ++i) {
            float b0 = 0.f, b1 = 0.f;
            for (int j = 0; j < K; ++j) {
                b0 += w1[j * OUT_W + ow0]     * tile[i][PADW + fov1[j * OUT_W + ow0]];
                b1 += w1[j * OUT_W + ow0 + 1] * tile[i][PADW + fov1[j * OUT_W + ow0 + 1]];
            }
            float2 res; res.x = b0; res.y = b1;
            *reinterpret_cast<float2*>(outp + (size_t)i * OUT_W) = res;
        }
    }
}

// ---------------------------------------------------------------------------
// Fully generic fallback (runtime K0/K1), parity-split tile (R4).
__global__ __launch_bounds__(256)
void fused_generic_kernel(const float* __restrict__ x,
                          const float* __restrict__ w0,
                          const int*   __restrict__ fov0,
                          const float* __restrict__ w1,
                          const int*   __restrict__ fov1,
                          float*       __restrict__ out,
                          int K0, int K1)
{
    __shared__ float tile[G][IN_W];
    const int t   = threadIdx.x;
    const int bc  = blockIdx.y;
    const int oh0 = blockIdx.x * G;
    const float4* xb = reinterpret_cast<const float4*>(x + (size_t)bc * IN_H * IN_W);

    for (int i = 0; i < G; ++i) {
        const int oh = oh0 + i;
        float ax = 0.f, ay = 0.f, az = 0.f, aw = 0.f;
        for (int j = 0; j < K0; ++j) {
            const int   r = fov0[j * OUT_H + oh];
            const float w = w0  [j * OUT_H + oh];
            const float4 v = xb[(size_t)r * (IN_W / 4) + t];
            ax += w * v.x; ay += w * v.y; az += w * v.z; aw += w * v.w;
        }
        float2 e; e.x = ax; e.y = az;
        float2 o; o.x = ay; o.y = aw;
        reinterpret_cast<float2*>(tile[i])[t]       = e;
        reinterpret_cast<float2*>(tile[i] + 512)[t] = o;
    }
    __syncthreads();

    float a0[G], a1[G];
#pragma unroll
    for (int i = 0; i < G; ++i) { a0[i] = 0.f; a1[i] = 0.f; }
    for (int j = 0; j < K1; ++j) {
        const float w_a = w1  [j * OUT_W + t];
        const float w_b = w1  [j * OUT_W + t + 256];
        const int   f_a = fov1[j * OUT_W + t];
        const int   f_b = fov1[j * OUT_W + t + 256];
        const int p_a = (f_a >> 1) + ((f_a & 1) << 9);
        const int p_b = (f_b >> 1) + ((f_b & 1) << 9);
#pragma unroll
        for (int i = 0; i < G; ++i) {
            a0[i] += w_a * tile[i][p_a];
            a1[i] += w_b * tile[i][p_b];
        }
    }
#pragma unroll
    for (int i = 0; i < G; ++i) {
        float* orow = out + ((size_t)bc * OUT_H + oh0 + i) * OUT_W;
        orow[t]       = a0[i];
        orow[t + 256] = a1[i];
    }
}

// ---------------------------------------------------------------------------

extern "C" void kernel_launch(void* const* d_in, const int* in_sizes, int n_in,
                              void* d_out, int out_size)
{
    const float* x    = (const float*)d_in[0];
    const float* w0   = (const float*)d_in[1];
    const int*   fov0 = (const int*)  d_in[2];
    const float* w1   = (const float*)d_in[3];
    const int*   fov1 = (const int*)  d_in[4];
    float*       out  = (float*)d_out;

    const int K0 = in_sizes[1] / OUT_H;   // vertical taps
    const int K1 = in_sizes[3] / OUT_W;   // horizontal taps

    dim3 grid(OUT_H / G, BC);

    if (K0 == K1) {
        switch (K0) {
        case 6:  fused_stream_kernel< 6><<<grid, 256>>>(x, w0, fov0, w1, fov1, out); return;
        case 7:  fused_stream_kernel< 7><<<grid, 256>>>(x, w0, fov0, w1, fov1, out); return;
        case 8:  fused_stream_kernel< 8><<<grid, 256>>>(x, w0, fov0, w1, fov1, out); return;
        case 9:  fused_stream_kernel< 9><<<grid, 256>>>(x, w0, fov0, w1, fov1, out); return;
        case 10: fused_stream_kernel<10><<<grid, 256>>>(x, w0, fov0, w1, fov1, out); return;
        case 11: fused_stream_kernel<11><<<grid, 256>>>(x, w0, fov0, w1, fov1, out); return;
        case 12: fused_stream_kernel<12><<<grid, 256>>>(x, w0, fov0, w1, fov1, out); return;
        default: break;
        }
    }
    fused_generic_kernel<<<grid, 256>>>(x, w0, fov0, w1, fov1, out, K0, K1);
}